// round 13
// baseline (speedup 1.0000x reference)
#include <cuda_runtime.h>
#include <cuda_fp16.h>
#include <cstdint>

#define MAX_N   131072
#define MAX_E   1700000
#define D       128
#define SCAN_B  512
#define MAX_BLK 256   // MAX_N / SCAN_B

#define A_STRIDE 136
#define W_STRIDE 136
#define GEMM_SMEM_BYTES ((64 * A_STRIDE + 128 * W_STRIDE) * 2)

// ---- scratch (__device__ globals; no allocations allowed) ----
__device__ __align__(16) __half2 g_bufh[(size_t)MAX_N * 64];  // h (then dinv*h), fp16
__device__ __align__(16) __half2 g_Wh2[64 * 128];             // W in fp16, row-major [k][n]
__device__ float g_dinv[MAX_N];
__device__ int   g_cnt[MAX_N];
__device__ int   g_rowptr[MAX_N + 1];
__device__ int   g_cur[MAX_N];
__device__ int   g_blk[MAX_BLK];
__device__ int   g_src[MAX_E];
__device__ int   g_e64;
__device__ int   g_tick;

// ---------------------------------------------------------------------------
__device__ __forceinline__ unsigned h2_as_u32(__half2 h) {
    union { __half2 h; unsigned u; } cvt; cvt.h = h; return cvt.u;
}
__device__ __forceinline__ __half2 u32_as_h2(unsigned u) {
    union { unsigned u; __half2 h; } cvt; cvt.u = u; return cvt.h;
}
__device__ __forceinline__ uint32_t smem_u32(const void* p) {
    return (uint32_t)__cvta_generic_to_shared(p);
}

// ---------------------------------------------------------------------------
// stream-1: W -> fp16 (independent of everything else)
__global__ void k_initW(const float* __restrict__ W) {
    const int j = blockIdx.x * blockDim.x + threadIdx.x;   // [0, 8192)
    const float2 w = ((const float2*)W)[j];
    g_Wh2[j] = __floats2half2_rn(w.x, w.y);
}

// stream-0: zero g_cnt + dtype probe + ticket reset.
__global__ void k_init(const void* __restrict__ edges, int N, int n) {
    __shared__ int bad;
    const int i = blockIdx.x * blockDim.x + threadIdx.x;
    if (i < n) g_cnt[i] = 0;
    if (blockIdx.x == 0) {
        if (threadIdx.x == 0) { bad = 0; g_tick = 0; }
        __syncthreads();
        if (threadIdx.x < 64) {
            long long v = ((const long long*)edges)[threadIdx.x];
            if (v < 0 || v >= (long long)N) atomicOr(&bad, 1);
        }
        __syncthreads();
        if (threadIdx.x == 0) g_e64 = bad ? 0 : 1;
    }
}

// histogram over edge targets, 2 edges/thread.
__global__ void k_hist(const void* __restrict__ edges, int E, int N) {
    const int t  = blockIdx.x * blockDim.x + threadIdx.x;
    const int e0 = t * 2;
    if (e0 >= E) return;
    const int e64 = g_e64;
    int c0, c1 = -1;
    const bool two = (e0 + 1 < E);
    if (e64) {
        const long long* p = (const long long*)edges + (long long)E + e0;
        if (two && ((E & 1) == 0)) {
            const longlong2 v = *(const longlong2*)p;
            c0 = (int)v.x; c1 = (int)v.y;
        } else { c0 = (int)p[0]; if (two) c1 = (int)p[1]; }
    } else {
        const int* p = (const int*)edges + (long long)E + e0;
        if (two && ((E & 1) == 0)) {
            const int2 v = *(const int2*)p;
            c0 = v.x; c1 = v.y;
        } else { c0 = p[0]; if (two) c1 = p[1]; }
    }
    if ((unsigned)c0 < (unsigned)N) atomicAdd(&g_cnt[c0], 1);
    if (two && (unsigned)c1 < (unsigned)N) atomicAdd(&g_cnt[c1], 1);
}

// per-block scan + dinv; last block scans block totals.
__global__ void k_scan1(int n, int nblk) {
    __shared__ int s[SCAN_B];
    __shared__ int isLast;
    const int tid = threadIdx.x;
    const int i   = blockIdx.x * SCAN_B + tid;
    const int v   = (i < n) ? g_cnt[i] : 0;
    if (i < n) g_dinv[i] = rsqrtf((float)(v + 1));
    s[tid] = v;
    __syncthreads();
    #pragma unroll
    for (int off = 1; off < SCAN_B; off <<= 1) {
        int t = (tid >= off) ? s[tid - off] : 0;
        __syncthreads();
        s[tid] += t;
        __syncthreads();
    }
    if (i < n) g_rowptr[i] = s[tid] - v;
    if (tid == SCAN_B - 1) g_blk[blockIdx.x] = s[tid];

    __threadfence();
    if (tid == 0) isLast = (atomicAdd(&g_tick, 1) == nblk - 1) ? 1 : 0;
    __syncthreads();
    if (isLast) {
        const int bv = (tid < nblk) ? g_blk[tid] : 0;
        s[tid] = (tid < MAX_BLK) ? bv : 0;
        __syncthreads();
        #pragma unroll
        for (int off = 1; off < MAX_BLK; off <<= 1) {
            int t = (tid >= off && tid < MAX_BLK) ? s[tid - off] : 0;
            __syncthreads();
            if (tid < MAX_BLK) s[tid] += t;
            __syncthreads();
        }
        if (tid < nblk) g_blk[tid] = s[tid] - bv;
    }
}

// ---------------------------------------------------------------------------
// Fused LayerNorm -> ReLU -> HMMA GEMM -> fp16 h (UNscaled). Stream-1 branch;
// overlaps the whole CSR chain.
__global__ void __launch_bounds__(256) fused_ln_gemm_kernel(
    const float* __restrict__ x,
    const float* __restrict__ gamma,
    const float* __restrict__ beta,
    int N)
{
    extern __shared__ __align__(16) __half smem[];
    __half* A_s = smem;                    // [64][A_STRIDE]
    __half* W_s = smem + 64 * A_STRIDE;    // [128][W_STRIDE]

    const int tid  = threadIdx.x;
    const int warp = tid >> 5;
    const int lane = tid & 31;
    const int node0 = blockIdx.x * 64;

    {
        const uint4* src = (const uint4*)g_Wh2;
        #pragma unroll
        for (int i = tid; i < 2048; i += 256) {
            const int row = i >> 4;
            const int c8  = i & 15;
            *(uint4*)&W_s[row * W_STRIDE + c8 * 8] = src[i];
        }
    }

    #pragma unroll
    for (int rr = 0; rr < 8; rr++) {
        const int n = warp * 8 + rr;
        const int node = node0 + n;
        float v0 = 0.f, v1 = 0.f, v2 = 0.f, v3 = 0.f;
        if (node < N) {
            const float* xr = x + (size_t)node * D;
            v0 = xr[lane]; v1 = xr[lane + 32]; v2 = xr[lane + 64]; v3 = xr[lane + 96];
        }
        float s  = v0 + v1 + v2 + v3;
        float sq = v0 * v0 + v1 * v1 + v2 * v2 + v3 * v3;
        #pragma unroll
        for (int off = 16; off; off >>= 1) {
            s  += __shfl_xor_sync(0xFFFFFFFFu, s,  off);
            sq += __shfl_xor_sync(0xFFFFFFFFu, sq, off);
        }
        const float mu  = s * (1.0f / 128.0f);
        const float var = sq * (1.0f / 128.0f) - mu * mu;
        const float rs  = rsqrtf(var + 1e-5f);
        __half* ar = &A_s[n * A_STRIDE];
        ar[lane]      = __float2half(fmaxf((v0 - mu) * rs * gamma[lane]      + beta[lane],      0.f));
        ar[lane + 32] = __float2half(fmaxf((v1 - mu) * rs * gamma[lane + 32] + beta[lane + 32], 0.f));
        ar[lane + 64] = __float2half(fmaxf((v2 - mu) * rs * gamma[lane + 64] + beta[lane + 64], 0.f));
        ar[lane + 96] = __float2half(fmaxf((v3 - mu) * rs * gamma[lane + 96] + beta[lane + 96], 0.f));
    }
    __syncthreads();

    const int wm = warp >> 2;
    const int wn = warp & 3;

    float acc[2][4][4];
    #pragma unroll
    for (int mt = 0; mt < 2; mt++)
        #pragma unroll
        for (int nn = 0; nn < 4; nn++)
            #pragma unroll
            for (int c = 0; c < 4; c++) acc[mt][nn][c] = 0.f;

    const uint32_t a_addr0 = smem_u32(&A_s[(wm * 32 + (lane & 15)) * A_STRIDE + (lane >> 4) * 8]);
    const uint32_t a_addr1 = a_addr0 + 16 * A_STRIDE * 2;
    const uint32_t b_addr0 = smem_u32(&W_s[(lane & 15) * W_STRIDE + wn * 32]);

    #pragma unroll
    for (int kk = 0; kk < 8; kk++) {
        uint32_t b0[4], b1[4];
        const uint32_t b_k = b_addr0 + kk * (16 * W_STRIDE * 2);
        #pragma unroll
        for (int nn = 0; nn < 4; nn++) {
            asm volatile("ldmatrix.sync.aligned.m8n8.x2.trans.shared.b16 {%0,%1}, [%2];"
                         : "=r"(b0[nn]), "=r"(b1[nn])
                         : "r"(b_k + nn * 16));
        }
        uint32_t a[2][4];
        asm volatile("ldmatrix.sync.aligned.m8n8.x4.shared.b16 {%0,%1,%2,%3}, [%4];"
                     : "=r"(a[0][0]), "=r"(a[0][1]), "=r"(a[0][2]), "=r"(a[0][3])
                     : "r"(a_addr0 + kk * 32));
        asm volatile("ldmatrix.sync.aligned.m8n8.x4.shared.b16 {%0,%1,%2,%3}, [%4];"
                     : "=r"(a[1][0]), "=r"(a[1][1]), "=r"(a[1][2]), "=r"(a[1][3])
                     : "r"(a_addr1 + kk * 32));
        #pragma unroll
        for (int mt = 0; mt < 2; mt++)
            #pragma unroll
            for (int nn = 0; nn < 4; nn++)
                asm volatile("mma.sync.aligned.m16n8k16.row.col.f32.f16.f16.f32 "
                             "{%0,%1,%2,%3}, {%4,%5,%6,%7}, {%8,%9}, {%0,%1,%2,%3};"
                             : "+f"(acc[mt][nn][0]), "+f"(acc[mt][nn][1]),
                               "+f"(acc[mt][nn][2]), "+f"(acc[mt][nn][3])
                             : "r"(a[mt][0]), "r"(a[mt][1]), "r"(a[mt][2]), "r"(a[mt][3]),
                               "r"(b0[nn]), "r"(b1[nn]));
    }

    const int group = lane >> 2;
    const int qp    = lane & 3;
    #pragma unroll
    for (int mt = 0; mt < 2; mt++) {
        const int r0 = node0 + wm * 32 + mt * 16 + group;
        const int r1 = r0 + 8;
        #pragma unroll
        for (int nn = 0; nn < 4; nn++) {
            const int col2 = wn * 16 + nn * 4 + qp;
            if (r0 < N)
                g_bufh[(size_t)r0 * 64 + col2] =
                    __floats2half2_rn(acc[mt][nn][0], acc[mt][nn][1]);
            if (r1 < N)
                g_bufh[(size_t)r1 * 64 + col2] =
                    __floats2half2_rn(acc[mt][nn][2], acc[mt][nn][3]);
        }
    }
}

// stream-1 tail: g_bufh[row] *= dinv[row]  (after GEMM + scan1)
__global__ void __launch_bounds__(256) k_scale(int N) {
    const int idx = blockIdx.x * blockDim.x + threadIdx.x;   // uint2 index
    const int total = N * 32;                                // 32 uint2 per row
    if (idx >= total) return;
    const int node = idx >> 5;
    const float dv = g_dinv[node];
    uint2 u = ((uint2*)g_bufh)[idx];
    const float2 f0 = __half22float2(u32_as_h2(u.x));
    const float2 f1 = __half22float2(u32_as_h2(u.y));
    u.x = h2_as_u32(__floats2half2_rn(f0.x * dv, f0.y * dv));
    u.y = h2_as_u32(__floats2half2_rn(f1.x * dv, f1.y * dv));
    ((uint2*)g_bufh)[idx] = u;
}

// ---------------------------------------------------------------------------
// stream-0: add block offsets; init cursors; set rowptr[N]
__global__ void k_scan3(int n, int E) {
    const int i = blockIdx.x * SCAN_B + threadIdx.x;
    if (i < n) {
        int r = g_rowptr[i] + g_blk[blockIdx.x];
        g_rowptr[i] = r;
        g_cur[i]    = r;
    }
    if (blockIdx.x == 0 && threadIdx.x == 0) g_rowptr[n] = E;
}

// CSR fill, 2 edges/thread.
__global__ void k_fill(const void* __restrict__ edges, int E, int N) {
    const int t  = blockIdx.x * blockDim.x + threadIdx.x;
    const int e0 = t * 2;
    if (e0 >= E) return;
    const int e64 = g_e64;
    const bool two = (e0 + 1 < E);
    int r0, c0, r1 = -1, c1 = -1;
    if (e64) {
        const long long* pr = (const long long*)edges + e0;
        const long long* pc = (const long long*)edges + (long long)E + e0;
        if (two) {
            const longlong2 vr = *(const longlong2*)pr;
            r0 = (int)vr.x; r1 = (int)vr.y;
            if ((E & 1) == 0) {
                const longlong2 vc = *(const longlong2*)pc;
                c0 = (int)vc.x; c1 = (int)vc.y;
            } else { c0 = (int)pc[0]; c1 = (int)pc[1]; }
        } else { r0 = (int)pr[0]; c0 = (int)pc[0]; }
    } else {
        const int* pr = (const int*)edges + e0;
        const int* pc = (const int*)edges + (long long)E + e0;
        if (two) {
            const int2 vr = *(const int2*)pr;
            r0 = vr.x; r1 = vr.y;
            if ((E & 1) == 0) {
                const int2 vc = *(const int2*)pc;
                c0 = vc.x; c1 = vc.y;
            } else { c0 = pc[0]; c1 = pc[1]; }
        } else { r0 = pr[0]; c0 = pc[0]; }
    }
    if ((unsigned)c0 < (unsigned)N && (unsigned)r0 < (unsigned)N) {
        int pos = atomicAdd(&g_cur[c0], 1);
        if (pos < MAX_E) g_src[pos] = r0;
    }
    if (two && (unsigned)c1 < (unsigned)N && (unsigned)r1 < (unsigned)N) {
        int pos = atomicAdd(&g_cur[c1], 1);
        if (pos < MAX_E) g_src[pos] = r1;
    }
}

// join: warp-per-node gather with fp16 tree reduction over 4-neighbor groups.
__global__ void __launch_bounds__(256) k_aggr(float* __restrict__ out,
                                              const float* __restrict__ bias, int N)
{
    const int gt   = blockIdx.x * blockDim.x + threadIdx.x;
    const int node = gt >> 5;
    const int lane = gt & 31;
    if (node >= N) return;

    const int start = g_rowptr[node];
    const int end   = g_rowptr[node + 1];

    float a0, a1, a2, a3;
    {
        const uint2 u = ((const uint2*)(g_bufh + (size_t)node * 64))[lane];
        const float2 f0 = __half22float2(u32_as_h2(u.x));
        const float2 f1 = __half22float2(u32_as_h2(u.y));
        a0 = f0.x; a1 = f0.y; a2 = f1.x; a3 = f1.y;
    }

    int k = start;
    for (; k + 4 <= end; k += 4) {
        const int j0 = g_src[k], j1 = g_src[k + 1], j2 = g_src[k + 2], j3 = g_src[k + 3];
        const uint2 u0 = ((const uint2*)(g_bufh + (size_t)j0 * 64))[lane];
        const uint2 u1 = ((const uint2*)(g_bufh + (size_t)j1 * 64))[lane];
        const uint2 u2 = ((const uint2*)(g_bufh + (size_t)j2 * 64))[lane];
        const uint2 u3 = ((const uint2*)(g_bufh + (size_t)j3 * 64))[lane];
        const __half2 sx = __hadd2(__hadd2(u32_as_h2(u0.x), u32_as_h2(u1.x)),
                                   __hadd2(u32_as_h2(u2.x), u32_as_h2(u3.x)));
        const __half2 sy = __hadd2(__hadd2(u32_as_h2(u0.y), u32_as_h2(u1.y)),
                                   __hadd2(u32_as_h2(u2.y), u32_as_h2(u3.y)));
        const float2 f0 = __half22float2(sx);
        const float2 f1 = __half22float2(sy);
        a0 += f0.x; a1 += f0.y; a2 += f1.x; a3 += f1.y;
    }
    for (; k < end; k++) {
        const int j = g_src[k];
        const uint2 u = ((const uint2*)(g_bufh + (size_t)j * 64))[lane];
        float2 f;
        f = __half22float2(u32_as_h2(u.x)); a0 += f.x; a1 += f.y;
        f = __half22float2(u32_as_h2(u.y)); a2 += f.x; a3 += f.y;
    }

    const float dvi = g_dinv[node];
    const float4 b = ((const float4*)bias)[lane];
    float4 r;
    r.x = a0 * dvi + b.x;
    r.y = a1 * dvi + b.y;
    r.z = a2 * dvi + b.z;
    r.w = a3 * dvi + b.w;
    ((float4*)(out + (size_t)node * D))[lane] = r;
}

// ---------------------------------------------------------------------------
extern "C" void kernel_launch(void* const* d_in, const int* in_sizes, int n_in,
                              void* d_out, int out_size)
{
    const float* x     = (const float*)d_in[0];
    const void*  edges = (const void*)d_in[1];
    const float* gamma = (const float*)d_in[2];
    const float* beta  = (const float*)d_in[3];
    const float* W     = (const float*)d_in[4];
    const float* bias  = (const float*)d_in[5];
    float*       out   = (float*)d_out;

    const int N = in_sizes[0] / D;
    const int E = in_sizes[1] / 2;
    const int nblk = (N + SCAN_B - 1) / SCAN_B;
    const int halfE = (E + 1) / 2;

    static cudaStream_t s1 = nullptr;
    static cudaEvent_t  evFork = nullptr, evDinv = nullptr, evJoin = nullptr;
    if (!s1) {
        cudaFuncSetAttribute(fused_ln_gemm_kernel,
                             cudaFuncAttributeMaxDynamicSharedMemorySize,
                             GEMM_SMEM_BYTES);
        cudaStreamCreateWithFlags(&s1, cudaStreamNonBlocking);
        cudaEventCreateWithFlags(&evFork, cudaEventDisableTiming);
        cudaEventCreateWithFlags(&evDinv, cudaEventDisableTiming);
        cudaEventCreateWithFlags(&evJoin, cudaEventDisableTiming);
    }

    // Legal capture fork: s1 must be forked FROM the origin stream before any
    // s1 launch, otherwise s1 work is not part of the captured graph.
    cudaEventRecord(evFork, 0);
    cudaStreamWaitEvent(s1, evFork, 0);

    // stream 1: W convert -> GEMM (h, unscaled) — overlaps the CSR chain
    k_initW<<<32, 256, 0, s1>>>(W);
    fused_ln_gemm_kernel<<<(N + 63) / 64, 256, GEMM_SMEM_BYTES, s1>>>(x, gamma, beta, N);

    // stream 0: CSR chain
    k_init<<<(N + 255) / 256, 256>>>(edges, N, N);
    k_hist<<<(halfE + 255) / 256, 256>>>(edges, E, N);
    k_scan1<<<nblk, SCAN_B>>>(N, nblk);
    cudaEventRecord(evDinv, 0);                    // dinv ready
    k_scan3<<<nblk, SCAN_B>>>(N, E);
    k_fill<<<(halfE + 255) / 256, 256>>>(edges, E, N);

    // stream 1 tail: scale h by dinv (needs GEMM done + dinv ready)
    cudaStreamWaitEvent(s1, evDinv, 0);
    k_scale<<<(N * 32 + 255) / 256, 256, 0, s1>>>(N);
    cudaEventRecord(evJoin, s1);

    // join and aggregate
    cudaStreamWaitEvent(0, evJoin, 0);
    k_aggr<<<(N * 32 + 255) / 256, 256>>>(out, bias, N);
}

// round 14
// speedup vs baseline: 1.0325x; 1.0325x over previous
#include <cuda_runtime.h>
#include <cuda_fp16.h>
#include <cstdint>

#define MAX_N   131072
#define MAX_E   1700000
#define D       128
#define SCAN_B  512
#define MAX_BLK 256   // MAX_N / SCAN_B

#define A_STRIDE 136
#define W_STRIDE 136
// 128-node tile: A_s[128][136] + W_s[128][136], halves
#define GEMM_SMEM_BYTES ((128 * A_STRIDE + 128 * W_STRIDE) * 2)

// ---- scratch (__device__ globals; no allocations allowed) ----
__device__ __align__(16) __half2 g_bufh[(size_t)MAX_N * 64];  // g = dinv*relu(LN(x))@W, fp16
__device__ __align__(16) __half2 g_Wh2[64 * 128];             // W in fp16, row-major [k][n]
__device__ float g_dinv[MAX_N];
__device__ int   g_cnt[MAX_N];
__device__ int   g_rowptr[MAX_N + 1];
__device__ int   g_cur[MAX_N];
__device__ int   g_blk[MAX_BLK];
__device__ int   g_src[MAX_E];
__device__ int   g_e64;
__device__ int   g_tick;

// ---------------------------------------------------------------------------
__device__ __forceinline__ unsigned h2_as_u32(__half2 h) {
    union { __half2 h; unsigned u; } cvt; cvt.h = h; return cvt.u;
}
__device__ __forceinline__ __half2 u32_as_h2(unsigned u) {
    union { unsigned u; __half2 h; } cvt; cvt.u = u; return cvt.h;
}
__device__ __forceinline__ uint32_t smem_u32(const void* p) {
    return (uint32_t)__cvta_generic_to_shared(p);
}

// ---------------------------------------------------------------------------
// stream-1: W -> fp16
__global__ void k_initW(const float* __restrict__ W) {
    const int j = blockIdx.x * blockDim.x + threadIdx.x;   // [0, 8192)
    const float2 w = ((const float2*)W)[j];
    g_Wh2[j] = __floats2half2_rn(w.x, w.y);
}

// stream-0: zero g_cnt + dtype probe + ticket reset.
__global__ void k_init(const void* __restrict__ edges, int N, int n) {
    __shared__ int bad;
    const int i = blockIdx.x * blockDim.x + threadIdx.x;
    if (i < n) g_cnt[i] = 0;
    if (blockIdx.x == 0) {
        if (threadIdx.x == 0) { bad = 0; g_tick = 0; }
        __syncthreads();
        if (threadIdx.x < 64) {
            long long v = ((const long long*)edges)[threadIdx.x];
            if (v < 0 || v >= (long long)N) atomicOr(&bad, 1);
        }
        __syncthreads();
        if (threadIdx.x == 0) g_e64 = bad ? 0 : 1;
    }
}

// histogram over edge targets, 2 edges/thread.
__global__ void k_hist(const void* __restrict__ edges, int E, int N) {
    const int t  = blockIdx.x * blockDim.x + threadIdx.x;
    const int e0 = t * 2;
    if (e0 >= E) return;
    const int e64 = g_e64;
    int c0, c1 = -1;
    const bool two = (e0 + 1 < E);
    if (e64) {
        const long long* p = (const long long*)edges + (long long)E + e0;
        if (two && ((E & 1) == 0)) {
            const longlong2 v = *(const longlong2*)p;
            c0 = (int)v.x; c1 = (int)v.y;
        } else { c0 = (int)p[0]; if (two) c1 = (int)p[1]; }
    } else {
        const int* p = (const int*)edges + (long long)E + e0;
        if (two && ((E & 1) == 0)) {
            const int2 v = *(const int2*)p;
            c0 = v.x; c1 = v.y;
        } else { c0 = p[0]; if (two) c1 = p[1]; }
    }
    if ((unsigned)c0 < (unsigned)N) atomicAdd(&g_cnt[c0], 1);
    if (two && (unsigned)c1 < (unsigned)N) atomicAdd(&g_cnt[c1], 1);
}

// per-block scan + dinv; last block scans block totals.
__global__ void k_scan1(int n, int nblk) {
    __shared__ int s[SCAN_B];
    __shared__ int isLast;
    const int tid = threadIdx.x;
    const int i   = blockIdx.x * SCAN_B + tid;
    const int v   = (i < n) ? g_cnt[i] : 0;
    if (i < n) g_dinv[i] = rsqrtf((float)(v + 1));
    s[tid] = v;
    __syncthreads();
    #pragma unroll
    for (int off = 1; off < SCAN_B; off <<= 1) {
        int t = (tid >= off) ? s[tid - off] : 0;
        __syncthreads();
        s[tid] += t;
        __syncthreads();
    }
    if (i < n) g_rowptr[i] = s[tid] - v;
    if (tid == SCAN_B - 1) g_blk[blockIdx.x] = s[tid];

    __threadfence();
    if (tid == 0) isLast = (atomicAdd(&g_tick, 1) == nblk - 1) ? 1 : 0;
    __syncthreads();
    if (isLast) {
        const int bv = (tid < nblk) ? g_blk[tid] : 0;
        s[tid] = (tid < MAX_BLK) ? bv : 0;
        __syncthreads();
        #pragma unroll
        for (int off = 1; off < MAX_BLK; off <<= 1) {
            int t = (tid >= off && tid < MAX_BLK) ? s[tid - off] : 0;
            __syncthreads();
            if (tid < MAX_BLK) s[tid] += t;
            __syncthreads();
        }
        if (tid < nblk) g_blk[tid] = s[tid] - bv;
    }
}

// ---------------------------------------------------------------------------
// Fused LayerNorm -> ReLU -> HMMA GEMM -> *dinv, fp16 out. (stream-1 branch)
// 512 threads, 128 nodes/block. Warp tile 32x32 (16 warps: 4 m x 4 n).
__global__ void __launch_bounds__(512) fused_ln_gemm_kernel(
    const float* __restrict__ x,
    const float* __restrict__ gamma,
    const float* __restrict__ beta,
    int N)
{
    extern __shared__ __align__(16) __half smem[];
    __half* A_s = smem;                     // [128][A_STRIDE]
    __half* W_s = smem + 128 * A_STRIDE;    // [128][W_STRIDE]

    const int tid  = threadIdx.x;
    const int warp = tid >> 5;
    const int lane = tid & 31;
    const int node0 = blockIdx.x * 128;

    // ---- Phase 0: stage fp16 W into shared ----
    {
        const uint4* src = (const uint4*)g_Wh2;   // 2048 uint4
        #pragma unroll
        for (int i = tid; i < 2048; i += 512) {
            const int row = i >> 4;
            const int c8  = i & 15;
            *(uint4*)&W_s[row * W_STRIDE + c8 * 8] = src[i];
        }
    }

    // ---- Phase A: LayerNorm + ReLU into A_s (fp16, row-major) ----
    #pragma unroll
    for (int rr = 0; rr < 8; rr++) {
        const int n = warp * 8 + rr;          // 16 warps x 8 = 128 rows
        const int node = node0 + n;
        float v0 = 0.f, v1 = 0.f, v2 = 0.f, v3 = 0.f;
        if (node < N) {
            const float* xr = x + (size_t)node * D;
            v0 = xr[lane]; v1 = xr[lane + 32]; v2 = xr[lane + 64]; v3 = xr[lane + 96];
        }
        float s  = v0 + v1 + v2 + v3;
        float sq = v0 * v0 + v1 * v1 + v2 * v2 + v3 * v3;
        #pragma unroll
        for (int off = 16; off; off >>= 1) {
            s  += __shfl_xor_sync(0xFFFFFFFFu, s,  off);
            sq += __shfl_xor_sync(0xFFFFFFFFu, sq, off);
        }
        const float mu  = s * (1.0f / 128.0f);
        const float var = sq * (1.0f / 128.0f) - mu * mu;
        const float rs  = rsqrtf(var + 1e-5f);
        __half* ar = &A_s[n * A_STRIDE];
        ar[lane]      = __float2half(fmaxf((v0 - mu) * rs * gamma[lane]      + beta[lane],      0.f));
        ar[lane + 32] = __float2half(fmaxf((v1 - mu) * rs * gamma[lane + 32] + beta[lane + 32], 0.f));
        ar[lane + 64] = __float2half(fmaxf((v2 - mu) * rs * gamma[lane + 64] + beta[lane + 64], 0.f));
        ar[lane + 96] = __float2half(fmaxf((v3 - mu) * rs * gamma[lane + 96] + beta[lane + 96], 0.f));
    }
    __syncthreads();

    // ---- Phase B: HMMA. 16 warps: wm = warp>>2 (0..3), wn = warp&3 (0..3) ----
    const int wm = warp >> 2;
    const int wn = warp & 3;

    float acc[2][4][4];
    #pragma unroll
    for (int mt = 0; mt < 2; mt++)
        #pragma unroll
        for (int nn = 0; nn < 4; nn++)
            #pragma unroll
            for (int c = 0; c < 4; c++) acc[mt][nn][c] = 0.f;

    const uint32_t a_addr0 = smem_u32(&A_s[(wm * 32 + (lane & 15)) * A_STRIDE + (lane >> 4) * 8]);
    const uint32_t a_addr1 = a_addr0 + 16 * A_STRIDE * 2;
    const uint32_t b_addr0 = smem_u32(&W_s[(lane & 15) * W_STRIDE + wn * 32]);

    #pragma unroll
    for (int kk = 0; kk < 8; kk++) {
        uint32_t b0[4], b1[4];
        const uint32_t b_k = b_addr0 + kk * (16 * W_STRIDE * 2);
        #pragma unroll
        for (int nn = 0; nn < 4; nn++) {
            asm volatile("ldmatrix.sync.aligned.m8n8.x2.trans.shared.b16 {%0,%1}, [%2];"
                         : "=r"(b0[nn]), "=r"(b1[nn])
                         : "r"(b_k + nn * 16));
        }
        uint32_t a[2][4];
        asm volatile("ldmatrix.sync.aligned.m8n8.x4.shared.b16 {%0,%1,%2,%3}, [%4];"
                     : "=r"(a[0][0]), "=r"(a[0][1]), "=r"(a[0][2]), "=r"(a[0][3])
                     : "r"(a_addr0 + kk * 32));
        asm volatile("ldmatrix.sync.aligned.m8n8.x4.shared.b16 {%0,%1,%2,%3}, [%4];"
                     : "=r"(a[1][0]), "=r"(a[1][1]), "=r"(a[1][2]), "=r"(a[1][3])
                     : "r"(a_addr1 + kk * 32));
        #pragma unroll
        for (int mt = 0; mt < 2; mt++)
            #pragma unroll
            for (int nn = 0; nn < 4; nn++)
                asm volatile("mma.sync.aligned.m16n8k16.row.col.f32.f16.f16.f32 "
                             "{%0,%1,%2,%3}, {%4,%5,%6,%7}, {%8,%9}, {%0,%1,%2,%3};"
                             : "+f"(acc[mt][nn][0]), "+f"(acc[mt][nn][1]),
                               "+f"(acc[mt][nn][2]), "+f"(acc[mt][nn][3])
                             : "r"(a[mt][0]), "r"(a[mt][1]), "r"(a[mt][2]), "r"(a[mt][3]),
                               "r"(b0[nn]), "r"(b1[nn]));
    }

    // ---- Epilogue: scale by dinv[node], fp16 store to g_bufh ----
    const int group = lane >> 2;
    const int qp    = lane & 3;
    #pragma unroll
    for (int mt = 0; mt < 2; mt++) {
        const int r0 = node0 + wm * 32 + mt * 16 + group;
        const int r1 = r0 + 8;
        const float dv0 = (r0 < N) ? g_dinv[r0] : 0.f;
        const float dv1 = (r1 < N) ? g_dinv[r1] : 0.f;
        #pragma unroll
        for (int nn = 0; nn < 4; nn++) {
            const int col2 = wn * 16 + nn * 4 + qp;
            if (r0 < N)
                g_bufh[(size_t)r0 * 64 + col2] =
                    __floats2half2_rn(acc[mt][nn][0] * dv0, acc[mt][nn][1] * dv0);
            if (r1 < N)
                g_bufh[(size_t)r1 * 64 + col2] =
                    __floats2half2_rn(acc[mt][nn][2] * dv1, acc[mt][nn][3] * dv1);
        }
    }
}

// ---------------------------------------------------------------------------
// stream-0: add block offsets; init cursors; set rowptr[N]
__global__ void k_scan3(int n, int E) {
    const int i = blockIdx.x * SCAN_B + threadIdx.x;
    if (i < n) {
        int r = g_rowptr[i] + g_blk[blockIdx.x];
        g_rowptr[i] = r;
        g_cur[i]    = r;
    }
    if (blockIdx.x == 0 && threadIdx.x == 0) g_rowptr[n] = E;
}

// CSR fill, 2 edges/thread.
__global__ void k_fill(const void* __restrict__ edges, int E, int N) {
    const int t  = blockIdx.x * blockDim.x + threadIdx.x;
    const int e0 = t * 2;
    if (e0 >= E) return;
    const int e64 = g_e64;
    const bool two = (e0 + 1 < E);
    int r0, c0, r1 = -1, c1 = -1;
    if (e64) {
        const long long* pr = (const long long*)edges + e0;
        const long long* pc = (const long long*)edges + (long long)E + e0;
        if (two) {
            const longlong2 vr = *(const longlong2*)pr;
            r0 = (int)vr.x; r1 = (int)vr.y;
            if ((E & 1) == 0) {
                const longlong2 vc = *(const longlong2*)pc;
                c0 = (int)vc.x; c1 = (int)vc.y;
            } else { c0 = (int)pc[0]; c1 = (int)pc[1]; }
        } else { r0 = (int)pr[0]; c0 = (int)pc[0]; }
    } else {
        const int* pr = (const int*)edges + e0;
        const int* pc = (const int*)edges + (long long)E + e0;
        if (two) {
            const int2 vr = *(const int2*)pr;
            r0 = vr.x; r1 = vr.y;
            if ((E & 1) == 0) {
                const int2 vc = *(const int2*)pc;
                c0 = vc.x; c1 = vc.y;
            } else { c0 = pc[0]; c1 = pc[1]; }
        } else { r0 = pr[0]; c0 = pc[0]; }
    }
    if ((unsigned)c0 < (unsigned)N && (unsigned)r0 < (unsigned)N) {
        int pos = atomicAdd(&g_cur[c0], 1);
        if (pos < MAX_E) g_src[pos] = r0;
    }
    if (two && (unsigned)c1 < (unsigned)N && (unsigned)r1 < (unsigned)N) {
        int pos = atomicAdd(&g_cur[c1], 1);
        if (pos < MAX_E) g_src[pos] = r1;
    }
}

// join: warp-per-node gather with fp16 tree reduction over 4-neighbor groups.
__global__ void __launch_bounds__(256) k_aggr(float* __restrict__ out,
                                              const float* __restrict__ bias, int N)
{
    const int gt   = blockIdx.x * blockDim.x + threadIdx.x;
    const int node = gt >> 5;
    const int lane = gt & 31;
    if (node >= N) return;

    const int start = g_rowptr[node];
    const int end   = g_rowptr[node + 1];

    float a0, a1, a2, a3;
    {
        const uint2 u = ((const uint2*)(g_bufh + (size_t)node * 64))[lane];
        const float2 f0 = __half22float2(u32_as_h2(u.x));
        const float2 f1 = __half22float2(u32_as_h2(u.y));
        a0 = f0.x; a1 = f0.y; a2 = f1.x; a3 = f1.y;
    }

    int k = start;
    for (; k + 4 <= end; k += 4) {
        const int j0 = g_src[k], j1 = g_src[k + 1], j2 = g_src[k + 2], j3 = g_src[k + 3];
        const uint2 u0 = ((const uint2*)(g_bufh + (size_t)j0 * 64))[lane];
        const uint2 u1 = ((const uint2*)(g_bufh + (size_t)j1 * 64))[lane];
        const uint2 u2 = ((const uint2*)(g_bufh + (size_t)j2 * 64))[lane];
        const uint2 u3 = ((const uint2*)(g_bufh + (size_t)j3 * 64))[lane];
        const __half2 sx = __hadd2(__hadd2(u32_as_h2(u0.x), u32_as_h2(u1.x)),
                                   __hadd2(u32_as_h2(u2.x), u32_as_h2(u3.x)));
        const __half2 sy = __hadd2(__hadd2(u32_as_h2(u0.y), u32_as_h2(u1.y)),
                                   __hadd2(u32_as_h2(u2.y), u32_as_h2(u3.y)));
        const float2 f0 = __half22float2(sx);
        const float2 f1 = __half22float2(sy);
        a0 += f0.x; a1 += f0.y; a2 += f1.x; a3 += f1.y;
    }
    for (; k < end; k++) {
        const int j = g_src[k];
        const uint2 u = ((const uint2*)(g_bufh + (size_t)j * 64))[lane];
        float2 f;
        f = __half22float2(u32_as_h2(u.x)); a0 += f.x; a1 += f.y;
        f = __half22float2(u32_as_h2(u.y)); a2 += f.x; a3 += f.y;
    }

    const float dvi = g_dinv[node];
    const float4 b = ((const float4*)bias)[lane];
    float4 r;
    r.x = a0 * dvi + b.x;
    r.y = a1 * dvi + b.y;
    r.z = a2 * dvi + b.z;
    r.w = a3 * dvi + b.w;
    ((float4*)(out + (size_t)node * D))[lane] = r;
}

// ---------------------------------------------------------------------------
extern "C" void kernel_launch(void* const* d_in, const int* in_sizes, int n_in,
                              void* d_out, int out_size)
{
    const float* x     = (const float*)d_in[0];
    const void*  edges = (const void*)d_in[1];
    const float* gamma = (const float*)d_in[2];
    const float* beta  = (const float*)d_in[3];
    const float* W     = (const float*)d_in[4];
    const float* bias  = (const float*)d_in[5];
    float*       out   = (float*)d_out;

    const int N = in_sizes[0] / D;
    const int E = in_sizes[1] / 2;
    const int nblk = (N + SCAN_B - 1) / SCAN_B;
    const int halfE = (E + 1) / 2;

    static cudaStream_t s1 = nullptr;
    static cudaEvent_t  evFork = nullptr, evJoin = nullptr;
    if (!s1) {
        cudaFuncSetAttribute(fused_ln_gemm_kernel,
                             cudaFuncAttributeMaxDynamicSharedMemorySize,
                             GEMM_SMEM_BYTES);
        cudaStreamCreateWithFlags(&s1, cudaStreamNonBlocking);
        cudaEventCreateWithFlags(&evFork, cudaEventDisableTiming);
        cudaEventCreateWithFlags(&evJoin, cudaEventDisableTiming);
    }

    // serial prefix on stream 0 (k_initW rides along; GEMM needs it + dinv)
    k_initW<<<32, 256>>>(W);
    k_init<<<(N + 255) / 256, 256>>>(edges, N, N);
    k_hist<<<(halfE + 255) / 256, 256>>>(edges, E, N);
    k_scan1<<<nblk, SCAN_B>>>(N, nblk);

    // fork: GEMM (scaled epilogue) on s1, CSR tail on stream 0
    cudaEventRecord(evFork, 0);
    cudaStreamWaitEvent(s1, evFork, 0);
    fused_ln_gemm_kernel<<<(N + 127) / 128, 512, GEMM_SMEM_BYTES, s1>>>(x, gamma, beta, N);
    cudaEventRecord(evJoin, s1);

    k_scan3<<<nblk, SCAN_B>>>(N, E);
    k_fill<<<(halfE + 255) / 256, 256>>>(edges, E, N);

    // join and aggregate
    cudaStreamWaitEvent(0, evJoin, 0);
    k_aggr<<<(N * 32 + 255) / 256, 256>>>(out, bias, N);
}